// round 13
// baseline (speedup 1.0000x reference)
#include <cuda_runtime.h>
#include <cuda_fp8.h>
#include <cuda_bf16.h>
#include <cstdint>
#include <math.h>

// Problem dims (fixed): x [2,4096,2048] fp32, w [2048,8192] e4m3 (promoted to f32
// by the harness), out [2,4096,8192] fp32.
#define GM 8192
#define GK 2048
#define GN 8192

// ---------------- scratch (device globals; no allocations allowed) ----------
__device__ uint8_t g_q [(size_t)GM * GK];   // quantized activations, [M,K] row-major
__device__ uint8_t g_wt[(size_t)GN * GK];   // weight as e4m3 bytes, transposed [N,K]

// ---------------- helpers ----------------------------------------------------
__device__ __forceinline__ uint32_t smem_u32(const void* p) {
    uint32_t a;
    asm("{ .reg .u64 t; cvta.to.shared.u64 t, %1; cvt.u32.u64 %0, t; }" : "=r"(a) : "l"(p));
    return a;
}

#define CP16(dst, src) \
    asm volatile("cp.async.cg.shared.global [%0], [%1], 16;" :: "r"(dst), "l"(src) : "memory")
#define CP_COMMIT() asm volatile("cp.async.commit_group;" ::: "memory")
#define CP_WAIT(n)  asm volatile("cp.async.wait_group %0;" :: "n"(n) : "memory")

#define LDSM4(r, addr) \
    asm volatile("ldmatrix.sync.aligned.m8n8.x4.shared.b16 {%0,%1,%2,%3}, [%4];" \
        : "=r"((r)[0]), "=r"((r)[1]), "=r"((r)[2]), "=r"((r)[3]) : "r"(addr))

#define MMA_FP8(d, a, b0, b1) \
    asm volatile("mma.sync.aligned.m16n8k32.row.col.f32.e4m3.e4m3.f32 " \
        "{%0,%1,%2,%3}, {%4,%5,%6,%7}, {%8,%9}, {%0,%1,%2,%3};" \
        : "+f"((d)[0]), "+f"((d)[1]), "+f"((d)[2]), "+f"((d)[3]) \
        : "r"((a)[0]), "r"((a)[1]), "r"((a)[2]), "r"((a)[3]), "r"(b0), "r"(b1))

__device__ __forceinline__ uint8_t f2e4m3(float v) {
    return (uint8_t)__nv_cvt_float_to_fp8(v, __NV_SATFINITE, __NV_E4M3);
}
__device__ __forceinline__ float e4m3f(uint8_t b) {
    __half_raw h = __nv_cvt_fp8_to_halfraw((__nv_fp8_storage_t)b, __NV_E4M3);
    return __half2float(*(__half*)&h);
}
__device__ __forceinline__ bool rt_ok(float v) {
    if (!isfinite(v)) return false;
    return e4m3f(f2e4m3(v)) == v;
}

// ---------------- kernel 1: fused prep (detect + convert/transpose + quant) --
#define PREP_BLKS ((GN / 64) * (GK / 64))             // 4096
#define QUANT_BLKS ((GM * GK) / (256 * 8))            // 8192

__global__ void __launch_bounds__(256) prep_kernel(const void* __restrict__ w,
                                                   const float* __restrict__ x,
                                                   const float* __restrict__ s_in) {
    const int t = threadIdx.x;
    if (blockIdx.x >= PREP_BLKS) {
        // ---- quant part ----
        const float s = *s_in;
        size_t i = (size_t)(blockIdx.x - PREP_BLKS) * 256 + t;   // one per 8 elems
        const float4 a = ((const float4*)x)[i * 2 + 0];
        const float4 b = ((const float4*)x)[i * 2 + 1];
        uint8_t q[8];
        q[0] = f2e4m3(a.x / s); q[1] = f2e4m3(a.y / s);
        q[2] = f2e4m3(a.z / s); q[3] = f2e4m3(a.w / s);
        q[4] = f2e4m3(b.x / s); q[5] = f2e4m3(b.y / s);
        q[6] = f2e4m3(b.z / s); q[7] = f2e4m3(b.w / s);
        ((uint2*)g_q)[i] = *(const uint2*)q;
        return;
    }

    // ---- weight prep part ----
    __shared__ uint8_t tile[64][68];            // [n_local][k_local], padded
    const int n0 = (blockIdx.x & 127) * 64;
    const int k0 = (blockIdx.x >> 7) * 64;

    // Inline dtype detection (fp8 promotion is lossless -> exact round-trip;
    // f32 checked first since f32-promoted data viewed as bf16 also passes).
    const int is_f32  = __syncthreads_and(rt_ok(((const float*)w)[t]));
    int is_bf16 = 0;
    if (!is_f32)
        is_bf16 = __syncthreads_and(rt_ok(__bfloat162float(((const __nv_bfloat16*)w)[t])));

    if (is_f32) {
        const float* wf = (const float*)w;
#pragma unroll
        for (int i = 0; i < 16; i++) {
            int e = t + i * 256;                // 4096 elems
            int r = e >> 6, c = e & 63;         // r = k_local, c = n_local
            tile[c][r] = f2e4m3(wf[(size_t)(k0 + r) * GN + n0 + c]);
        }
    } else if (is_bf16) {
        const __nv_bfloat16* wb = (const __nv_bfloat16*)w;
#pragma unroll
        for (int i = 0; i < 16; i++) {
            int e = t + i * 256;
            int r = e >> 6, c = e & 63;
            tile[c][r] = f2e4m3(__bfloat162float(wb[(size_t)(k0 + r) * GN + n0 + c]));
        }
    } else {
        const uint8_t* w8 = (const uint8_t*)w;
#pragma unroll
        for (int i = 0; i < 4; i++) {
            int idx = t + i * 256;
            int r = idx >> 4, wc = idx & 15;
            uint32_t v = *(const uint32_t*)(w8 + (size_t)(k0 + r) * GN + n0 + wc * 4);
            tile[wc * 4 + 0][r] = (uint8_t)(v);
            tile[wc * 4 + 1][r] = (uint8_t)(v >> 8);
            tile[wc * 4 + 2][r] = (uint8_t)(v >> 16);
            tile[wc * 4 + 3][r] = (uint8_t)(v >> 24);
        }
    }
    __syncthreads();
#pragma unroll
    for (int i = 0; i < 4; i++) {
        int idx = t + i * 256;
        int r = idx >> 4, wc = idx & 15;        // r = n_local, wc = word over k
        uint32_t v = (uint32_t)tile[r][wc * 4 + 0]
                   | ((uint32_t)tile[r][wc * 4 + 1] << 8)
                   | ((uint32_t)tile[r][wc * 4 + 2] << 16)
                   | ((uint32_t)tile[r][wc * 4 + 3] << 24);
        *(uint32_t*)(g_wt + (size_t)(n0 + r) * GK + k0 + wc * 4) = v;
    }
}

// ---------------- kernel 2: FP8 GEMM (mma.sync, 64x64 warp tiles) -----------
// CTA 128x128x128, 4 warps, 3-stage 32KB ring (98KB smem) -> 2 CTAs/SM.
#define TILE_M 128
#define TILE_N 128
#define TILE_K 128
#define STAGES 3
#define KT (GK / TILE_K)          // 16
#define NTHREADS 128

static constexpr int A_BYTES     = TILE_M * TILE_K;       // 16384
static constexpr int STAGE_BYTES = 2 * A_BYTES;           // 32768
static constexpr int SMEM_DYN    = STAGES * STAGE_BYTES;  // 98304

// One tile-row per 128B smem row; SW128 XOR of the 16B chunk index.
// Identity used below: sw_off(row, kk*2+kh) = sw_off(row, kh) ^ (kk<<5).
__device__ __forceinline__ uint32_t sw_off(int row, int kc) {
    return ((uint32_t)row << 7) + ((uint32_t)((kc ^ (row & 7))) << 4);
}

__device__ __forceinline__ void load_stage(uint32_t sb, int tid,
                                           const uint8_t* __restrict__ gA0,
                                           const uint8_t* __restrict__ gB0,
                                           int kt, int s) {
    const uint32_t base = sb + (uint32_t)s * STAGE_BYTES;
    const uint8_t* ga = gA0 + (size_t)kt * TILE_K;
    const uint8_t* gb = gB0 + (size_t)kt * TILE_K;
#pragma unroll
    for (int i = 0; i < 8; i++) {                     // A: 1024 chunks / 128 thr
        int c = tid + i * NTHREADS;
        int r = c >> 3, kc = c & 7;
        CP16(base + sw_off(r, kc), ga + (size_t)r * GK + kc * 16);
    }
#pragma unroll
    for (int i = 0; i < 8; i++) {                     // B: 1024 chunks
        int c = tid + i * NTHREADS;
        int r = c >> 3, kc = c & 7;
        CP16(base + A_BYTES + sw_off(r, kc), gb + (size_t)r * GK + kc * 16);
    }
    CP_COMMIT();
}

struct Frag { float acc[4][8][4]; };   // [m16][n8][quad] — 128 regs

__device__ __forceinline__ void mma_frags(Frag& f, uint32_t a[4][4], uint32_t b[4][4]) {
#pragma unroll
    for (int mt = 0; mt < 4; mt++)
#pragma unroll
        for (int p = 0; p < 4; p++) {
            MMA_FP8(f.acc[mt][p * 2 + 0], a[mt], b[p][0], b[p][1]);
            MMA_FP8(f.acc[mt][p * 2 + 1], a[mt], b[p][2], b[p][3]);
        }
}

// Fragments double-buffered; LDSM addresses derived from 8 precomputed
// per-thread offsets via a single XOR per load (kk axis = XOR with kk<<5).
__device__ __forceinline__ void compute_stage(uint32_t stage, Frag& f,
                                              const uint32_t aoff[4],
                                              const uint32_t boff[4],
                                              const uint32_t xv[4]) {
    uint32_t aaddr[4], baddr[4];
#pragma unroll
    for (int mt = 0; mt < 4; mt++) aaddr[mt] = stage + aoff[mt];
#pragma unroll
    for (int p = 0; p < 4; p++)    baddr[p]  = stage + boff[p];

    uint32_t a[2][4][4], b[2][4][4];
#pragma unroll
    for (int mt = 0; mt < 4; mt++) LDSM4(a[0][mt], aaddr[mt] ^ xv[0]);
#pragma unroll
    for (int p = 0; p < 4; p++)    LDSM4(b[0][p],  baddr[p]  ^ xv[0]);
#pragma unroll
    for (int i = 0; i < 4; i++) {
        if (i < 3) {
#pragma unroll
            for (int mt = 0; mt < 4; mt++)
                LDSM4(a[(i + 1) & 1][mt], aaddr[mt] ^ xv[i + 1]);
#pragma unroll
            for (int p = 0; p < 4; p++)
                LDSM4(b[(i + 1) & 1][p],  baddr[p]  ^ xv[i + 1]);
        }
        mma_frags(f, a[i & 1], b[i & 1]);
    }
}

__global__ void __launch_bounds__(NTHREADS, 1)
gemm_kernel(const float* __restrict__ wscale, const float* __restrict__ iscale,
            const float* __restrict__ bias, float* __restrict__ out) {
    extern __shared__ uint8_t smem[];
    const uint32_t sb = smem_u32(smem);

    const int tid = threadIdx.x, wid = tid >> 5, lane = tid & 31;
    const int warp_m = wid & 1, warp_n = wid >> 1;     // 2x2 warp grid
    const int m0 = blockIdx.y * TILE_M;
    const int n0 = blockIdx.x * TILE_N;
    const int skew = (wid + 2 * ((blockIdx.x + blockIdx.y) & 1)) & 3;

    // ldmatrix lane geometry
    const int a_m  = warp_m * 64 + (lane & 15);        // + mt*16
    const int a_kh = lane >> 4;                        // 16B half of K=32
    const int b_n  = warp_n * 64 + (lane & 7) + ((lane >> 4) << 3);  // + p*16
    const int b_kh = (lane >> 3) & 1;

    // Precomputed stage-relative LDSM offsets (kk=0) and kk XOR masks.
    uint32_t aoff[4], boff[4], xv[4];
#pragma unroll
    for (int mt = 0; mt < 4; mt++) aoff[mt] = sw_off(a_m + mt * 16, a_kh);
#pragma unroll
    for (int p = 0; p < 4; p++)    boff[p]  = A_BYTES + sw_off(b_n + p * 16, b_kh);
#pragma unroll
    for (int i = 0; i < 4; i++)    xv[i]    = (uint32_t)(((skew + i) & 3) << 5);

    Frag f;
#pragma unroll
    for (int i = 0; i < 4; i++)
#pragma unroll
        for (int j = 0; j < 8; j++)
#pragma unroll
            for (int q = 0; q < 4; q++) f.acc[i][j][q] = 0.0f;

    const uint8_t* gA0 = g_q  + (size_t)m0 * GK;
    const uint8_t* gB0 = g_wt + (size_t)n0 * GK;

    // Prologue: stages 0,1 in flight
    load_stage(sb, tid, gA0, gB0, 0, 0);
    load_stage(sb, tid, gA0, gB0, 1, 1);

    int s_cur = 0, s_next = 2;
#pragma unroll 1
    for (int kt = 0; kt < KT; kt++) {
        if (kt == KT - 1) { CP_WAIT(0); }   // last group has no successor pending
        else              { CP_WAIT(1); }   // groups complete in commit order
        __syncthreads();                    // all warps consumed stage kt-1
        compute_stage(sb + (uint32_t)s_cur * STAGE_BYTES, f, aoff, boff, xv);
        // Loads AFTER compute: slot s_next (= stage kt-1's slot) was proven
        // consumed by the barrier above; issue sits off the pipe-critical path.
        if (kt + 2 < KT)
            load_stage(sb, tid, gA0, gB0, kt + 2, s_next);
        if (++s_cur == STAGES) s_cur = 0;
        if (++s_next == STAGES) s_next = 0;
    }

    // Epilogue: out = acc * (s_in*s_w) + bias
    const float s = wscale[0] * iscale[0];
    const int g = lane >> 2, tig = lane & 3;
#pragma unroll
    for (int nt = 0; nt < 8; nt++) {
        const int n = n0 + warp_n * 64 + nt * 8 + tig * 2;
        const float2 bv = *(const float2*)(bias + n);
#pragma unroll
        for (int mt = 0; mt < 4; mt++) {
            const int m = m0 + warp_m * 64 + mt * 16 + g;
            float2 v0, v1;
            v0.x = f.acc[mt][nt][0] * s + bv.x;
            v0.y = f.acc[mt][nt][1] * s + bv.y;
            v1.x = f.acc[mt][nt][2] * s + bv.x;
            v1.y = f.acc[mt][nt][3] * s + bv.y;
            *(float2*)(out + (size_t)m * GN + n)       = v0;
            *(float2*)(out + (size_t)(m + 8) * GN + n) = v1;
        }
    }
}

// ---------------- launcher ---------------------------------------------------
extern "C" void kernel_launch(void* const* d_in, const int* in_sizes, int n_in,
                              void* d_out, int out_size) {
    const float*   x      = (const float*)d_in[0];
    const void*    w      = d_in[1];
    const float*   wscale = (const float*)d_in[2];
    const float*   iscale = (const float*)d_in[3];
    const float*   bias   = (const float*)d_in[4];
    float*         out    = (float*)d_out;

    prep_kernel<<<PREP_BLKS + QUANT_BLKS, 256>>>(w, x, iscale);

    cudaFuncSetAttribute(gemm_kernel, cudaFuncAttributeMaxDynamicSharedMemorySize, SMEM_DYN);
    gemm_kernel<<<dim3(GN / TILE_N, GM / TILE_M), NTHREADS, SMEM_DYN>>>(wscale, iscale, bias, out);
}

// round 14
// speedup vs baseline: 1.0031x; 1.0031x over previous
#include <cuda_runtime.h>
#include <cuda_fp8.h>
#include <cuda_bf16.h>
#include <cstdint>
#include <math.h>

// Problem dims (fixed): x [2,4096,2048] fp32, w [2048,8192] e4m3 (promoted to f32
// by the harness), out [2,4096,8192] fp32.
#define GM 8192
#define GK 2048
#define GN 8192

// ---------------- scratch (device globals; no allocations allowed) ----------
__device__ uint8_t g_q [(size_t)GM * GK];   // quantized activations, [M,K] row-major
__device__ uint8_t g_wt[(size_t)GN * GK];   // weight as e4m3 bytes, transposed [N,K]

// ---------------- helpers ----------------------------------------------------
__device__ __forceinline__ uint32_t smem_u32(const void* p) {
    uint32_t a;
    asm("{ .reg .u64 t; cvta.to.shared.u64 t, %1; cvt.u32.u64 %0, t; }" : "=r"(a) : "l"(p));
    return a;
}

#define CP16(dst, src) \
    asm volatile("cp.async.cg.shared.global [%0], [%1], 16;" :: "r"(dst), "l"(src) : "memory")
#define CP_COMMIT() asm volatile("cp.async.commit_group;" ::: "memory")
#define CP_WAIT(n)  asm volatile("cp.async.wait_group %0;" :: "n"(n) : "memory")

#define LDSM4(r, addr) \
    asm volatile("ldmatrix.sync.aligned.m8n8.x4.shared.b16 {%0,%1,%2,%3}, [%4];" \
        : "=r"((r)[0]), "=r"((r)[1]), "=r"((r)[2]), "=r"((r)[3]) : "r"(addr))

#define MMA_FP8(d, a, b0, b1) \
    asm volatile("mma.sync.aligned.m16n8k32.row.col.f32.e4m3.e4m3.f32 " \
        "{%0,%1,%2,%3}, {%4,%5,%6,%7}, {%8,%9}, {%0,%1,%2,%3};" \
        : "+f"((d)[0]), "+f"((d)[1]), "+f"((d)[2]), "+f"((d)[3]) \
        : "r"((a)[0]), "r"((a)[1]), "r"((a)[2]), "r"((a)[3]), "r"(b0), "r"(b1))

__device__ __forceinline__ uint8_t f2e4m3(float v) {
    return (uint8_t)__nv_cvt_float_to_fp8(v, __NV_SATFINITE, __NV_E4M3);
}
__device__ __forceinline__ float e4m3f(uint8_t b) {
    __half_raw h = __nv_cvt_fp8_to_halfraw((__nv_fp8_storage_t)b, __NV_E4M3);
    return __half2float(*(__half*)&h);
}
__device__ __forceinline__ bool rt_ok(float v) {
    if (!isfinite(v)) return false;
    return e4m3f(f2e4m3(v)) == v;
}

// ---------------- kernel 1: fused prep (detect + convert/transpose + quant) --
#define PREP_BLKS ((GN / 64) * (GK / 64))             // 4096
#define QUANT_BLKS ((GM * GK) / (256 * 8))            // 8192

__global__ void __launch_bounds__(256) prep_kernel(const void* __restrict__ w,
                                                   const float* __restrict__ x,
                                                   const float* __restrict__ s_in) {
    const int t = threadIdx.x;
    if (blockIdx.x >= PREP_BLKS) {
        // ---- quant part ----
        const float s = *s_in;
        size_t i = (size_t)(blockIdx.x - PREP_BLKS) * 256 + t;   // one per 8 elems
        const float4 a = ((const float4*)x)[i * 2 + 0];
        const float4 b = ((const float4*)x)[i * 2 + 1];
        uint8_t q[8];
        q[0] = f2e4m3(a.x / s); q[1] = f2e4m3(a.y / s);
        q[2] = f2e4m3(a.z / s); q[3] = f2e4m3(a.w / s);
        q[4] = f2e4m3(b.x / s); q[5] = f2e4m3(b.y / s);
        q[6] = f2e4m3(b.z / s); q[7] = f2e4m3(b.w / s);
        ((uint2*)g_q)[i] = *(const uint2*)q;
        return;
    }

    // ---- weight prep part ----
    __shared__ uint8_t tile[64][68];            // [n_local][k_local], padded
    const int n0 = (blockIdx.x & 127) * 64;
    const int k0 = (blockIdx.x >> 7) * 64;

    // Inline dtype detection (fp8 promotion is lossless -> exact round-trip;
    // f32 checked first since f32-promoted data viewed as bf16 also passes).
    const int is_f32  = __syncthreads_and(rt_ok(((const float*)w)[t]));
    int is_bf16 = 0;
    if (!is_f32)
        is_bf16 = __syncthreads_and(rt_ok(__bfloat162float(((const __nv_bfloat16*)w)[t])));

    if (is_f32) {
        const float* wf = (const float*)w;
#pragma unroll
        for (int i = 0; i < 16; i++) {
            int e = t + i * 256;                // 4096 elems
            int r = e >> 6, c = e & 63;         // r = k_local, c = n_local
            tile[c][r] = f2e4m3(wf[(size_t)(k0 + r) * GN + n0 + c]);
        }
    } else if (is_bf16) {
        const __nv_bfloat16* wb = (const __nv_bfloat16*)w;
#pragma unroll
        for (int i = 0; i < 16; i++) {
            int e = t + i * 256;
            int r = e >> 6, c = e & 63;
            tile[c][r] = f2e4m3(__bfloat162float(wb[(size_t)(k0 + r) * GN + n0 + c]));
        }
    } else {
        const uint8_t* w8 = (const uint8_t*)w;
#pragma unroll
        for (int i = 0; i < 4; i++) {
            int idx = t + i * 256;
            int r = idx >> 4, wc = idx & 15;
            uint32_t v = *(const uint32_t*)(w8 + (size_t)(k0 + r) * GN + n0 + wc * 4);
            tile[wc * 4 + 0][r] = (uint8_t)(v);
            tile[wc * 4 + 1][r] = (uint8_t)(v >> 8);
            tile[wc * 4 + 2][r] = (uint8_t)(v >> 16);
            tile[wc * 4 + 3][r] = (uint8_t)(v >> 24);
        }
    }
    __syncthreads();
#pragma unroll
    for (int i = 0; i < 4; i++) {
        int idx = t + i * 256;
        int r = idx >> 4, wc = idx & 15;        // r = n_local, wc = word over k
        uint32_t v = (uint32_t)tile[r][wc * 4 + 0]
                   | ((uint32_t)tile[r][wc * 4 + 1] << 8)
                   | ((uint32_t)tile[r][wc * 4 + 2] << 16)
                   | ((uint32_t)tile[r][wc * 4 + 3] << 24);
        *(uint32_t*)(g_wt + (size_t)(n0 + r) * GK + k0 + wc * 4) = v;
    }
}

// ---------------- kernel 2: FP8 GEMM (mma.sync, 64x64 warp tiles) -----------
// CTA 128x128x128, 4 warps, 3-stage 32KB ring (98KB smem) -> 2 CTAs/SM.
// Structure = R12 (loads BEFORE compute — proven best prefetch placement);
// addressing = R13 (XOR-derived LDSM addresses — proven int-pipe reduction).
#define TILE_M 128
#define TILE_N 128
#define TILE_K 128
#define STAGES 3
#define KT (GK / TILE_K)          // 16
#define NTHREADS 128

static constexpr int A_BYTES     = TILE_M * TILE_K;       // 16384
static constexpr int STAGE_BYTES = 2 * A_BYTES;           // 32768
static constexpr int SMEM_DYN    = STAGES * STAGE_BYTES;  // 98304

// One tile-row per 128B smem row; SW128 XOR of the 16B chunk index.
// Identity used below: sw_off(row, kk*2+kh) = sw_off(row, kh) ^ (kk<<5).
__device__ __forceinline__ uint32_t sw_off(int row, int kc) {
    return ((uint32_t)row << 7) + ((uint32_t)((kc ^ (row & 7))) << 4);
}

__device__ __forceinline__ void load_stage(uint32_t sb, int tid,
                                           const uint8_t* __restrict__ gA0,
                                           const uint8_t* __restrict__ gB0,
                                           int kt, int s) {
    const uint32_t base = sb + (uint32_t)s * STAGE_BYTES;
    const uint8_t* ga = gA0 + (size_t)kt * TILE_K;
    const uint8_t* gb = gB0 + (size_t)kt * TILE_K;
#pragma unroll
    for (int i = 0; i < 8; i++) {                     // A: 1024 chunks / 128 thr
        int c = tid + i * NTHREADS;
        int r = c >> 3, kc = c & 7;
        CP16(base + sw_off(r, kc), ga + (size_t)r * GK + kc * 16);
    }
#pragma unroll
    for (int i = 0; i < 8; i++) {                     // B: 1024 chunks
        int c = tid + i * NTHREADS;
        int r = c >> 3, kc = c & 7;
        CP16(base + A_BYTES + sw_off(r, kc), gb + (size_t)r * GK + kc * 16);
    }
    CP_COMMIT();
}

struct Frag { float acc[4][8][4]; };   // [m16][n8][quad] — 128 regs

__device__ __forceinline__ void mma_frags(Frag& f, uint32_t a[4][4], uint32_t b[4][4]) {
#pragma unroll
    for (int mt = 0; mt < 4; mt++)
#pragma unroll
        for (int p = 0; p < 4; p++) {
            MMA_FP8(f.acc[mt][p * 2 + 0], a[mt], b[p][0], b[p][1]);
            MMA_FP8(f.acc[mt][p * 2 + 1], a[mt], b[p][2], b[p][3]);
        }
}

// Fragments double-buffered; LDSM addresses derived from 8 precomputed
// per-thread offsets via a single XOR per load (kk axis = XOR with kk<<5).
__device__ __forceinline__ void compute_stage(uint32_t stage, Frag& f,
                                              const uint32_t aoff[4],
                                              const uint32_t boff[4],
                                              const uint32_t xv[4]) {
    uint32_t aaddr[4], baddr[4];
#pragma unroll
    for (int mt = 0; mt < 4; mt++) aaddr[mt] = stage + aoff[mt];
#pragma unroll
    for (int p = 0; p < 4; p++)    baddr[p]  = stage + boff[p];

    uint32_t a[2][4][4], b[2][4][4];
#pragma unroll
    for (int mt = 0; mt < 4; mt++) LDSM4(a[0][mt], aaddr[mt] ^ xv[0]);
#pragma unroll
    for (int p = 0; p < 4; p++)    LDSM4(b[0][p],  baddr[p]  ^ xv[0]);
#pragma unroll
    for (int i = 0; i < 4; i++) {
        if (i < 3) {
#pragma unroll
            for (int mt = 0; mt < 4; mt++)
                LDSM4(a[(i + 1) & 1][mt], aaddr[mt] ^ xv[i + 1]);
#pragma unroll
            for (int p = 0; p < 4; p++)
                LDSM4(b[(i + 1) & 1][p],  baddr[p]  ^ xv[i + 1]);
        }
        mma_frags(f, a[i & 1], b[i & 1]);
    }
}

__global__ void __launch_bounds__(NTHREADS, 1)
gemm_kernel(const float* __restrict__ wscale, const float* __restrict__ iscale,
            const float* __restrict__ bias, float* __restrict__ out) {
    extern __shared__ uint8_t smem[];
    const uint32_t sb = smem_u32(smem);

    const int tid = threadIdx.x, wid = tid >> 5, lane = tid & 31;
    const int warp_m = wid & 1, warp_n = wid >> 1;     // 2x2 warp grid
    const int m0 = blockIdx.y * TILE_M;
    const int n0 = blockIdx.x * TILE_N;
    const int skew = (wid + 2 * ((blockIdx.x + blockIdx.y) & 1)) & 3;

    // ldmatrix lane geometry
    const int a_m  = warp_m * 64 + (lane & 15);        // + mt*16
    const int a_kh = lane >> 4;                        // 16B half of K=32
    const int b_n  = warp_n * 64 + (lane & 7) + ((lane >> 4) << 3);  // + p*16
    const int b_kh = (lane >> 3) & 1;

    // Precomputed stage-relative LDSM offsets (kk=0) and kk XOR masks.
    uint32_t aoff[4], boff[4], xv[4];
#pragma unroll
    for (int mt = 0; mt < 4; mt++) aoff[mt] = sw_off(a_m + mt * 16, a_kh);
#pragma unroll
    for (int p = 0; p < 4; p++)    boff[p]  = A_BYTES + sw_off(b_n + p * 16, b_kh);
#pragma unroll
    for (int i = 0; i < 4; i++)    xv[i]    = (uint32_t)(((skew + i) & 3) << 5);

    Frag f;
#pragma unroll
    for (int i = 0; i < 4; i++)
#pragma unroll
        for (int j = 0; j < 8; j++)
#pragma unroll
            for (int q = 0; q < 4; q++) f.acc[i][j][q] = 0.0f;

    const uint8_t* gA0 = g_q  + (size_t)m0 * GK;
    const uint8_t* gB0 = g_wt + (size_t)n0 * GK;

    // Prologue: stages 0,1 in flight
    load_stage(sb, tid, gA0, gB0, 0, 0);
    load_stage(sb, tid, gA0, gB0, 1, 1);

    int s_cur = 0, s_next = 2;
#pragma unroll 1
    for (int kt = 0; kt < KT - 1; kt++) {
        CP_WAIT(1);            // stage kt data landed
        __syncthreads();       // s_next's old contents fully consumed
        if (kt + 2 < KT)
            load_stage(sb, tid, gA0, gB0, kt + 2, s_next);
        compute_stage(sb + (uint32_t)s_cur * STAGE_BYTES, f, aoff, boff, xv);
        if (++s_cur == STAGES) s_cur = 0;
        if (++s_next == STAGES) s_next = 0;
    }
    CP_WAIT(0);
    __syncthreads();
    compute_stage(sb + (uint32_t)s_cur * STAGE_BYTES, f, aoff, boff, xv);

    // Epilogue: out = acc * (s_in*s_w) + bias
    const float s = wscale[0] * iscale[0];
    const int g = lane >> 2, tig = lane & 3;
#pragma unroll
    for (int nt = 0; nt < 8; nt++) {
        const int n = n0 + warp_n * 64 + nt * 8 + tig * 2;
        const float2 bv = *(const float2*)(bias + n);
#pragma unroll
        for (int mt = 0; mt < 4; mt++) {
            const int m = m0 + warp_m * 64 + mt * 16 + g;
            float2 v0, v1;
            v0.x = f.acc[mt][nt][0] * s + bv.x;
            v0.y = f.acc[mt][nt][1] * s + bv.y;
            v1.x = f.acc[mt][nt][2] * s + bv.x;
            v1.y = f.acc[mt][nt][3] * s + bv.y;
            *(float2*)(out + (size_t)m * GN + n)       = v0;
            *(float2*)(out + (size_t)(m + 8) * GN + n) = v1;
        }
    }
}

// ---------------- launcher ---------------------------------------------------
extern "C" void kernel_launch(void* const* d_in, const int* in_sizes, int n_in,
                              void* d_out, int out_size) {
    const float*   x      = (const float*)d_in[0];
    const void*    w      = d_in[1];
    const float*   wscale = (const float*)d_in[2];
    const float*   iscale = (const float*)d_in[3];
    const float*   bias   = (const float*)d_in[4];
    float*         out    = (float*)d_out;

    prep_kernel<<<PREP_BLKS + QUANT_BLKS, 256>>>(w, x, iscale);

    cudaFuncSetAttribute(gemm_kernel, cudaFuncAttributeMaxDynamicSharedMemorySize, SMEM_DYN);
    gemm_kernel<<<dim3(GN / TILE_N, GM / TILE_M), NTHREADS, SMEM_DYN>>>(wscale, iscale, bias, out);
}

// round 15
// speedup vs baseline: 1.0403x; 1.0370x over previous
#include <cuda_runtime.h>
#include <cuda_fp8.h>
#include <cuda_bf16.h>
#include <cstdint>
#include <math.h>

// Problem dims (fixed): x [2,4096,2048] fp32, w [2048,8192] e4m3 (promoted to f32
// by the harness), out [2,4096,8192] fp32.
#define GM 8192
#define GK 2048
#define GN 8192

// ---------------- scratch (device globals; no allocations allowed) ----------
__device__ uint8_t g_q [(size_t)GM * GK];   // quantized activations, [M,K] row-major
__device__ uint8_t g_wt[(size_t)GN * GK];   // weight as e4m3 bytes, transposed [N,K]

// ---------------- helpers ----------------------------------------------------
__device__ __forceinline__ uint32_t smem_u32(const void* p) {
    uint32_t a;
    asm("{ .reg .u64 t; cvta.to.shared.u64 t, %1; cvt.u32.u64 %0, t; }" : "=r"(a) : "l"(p));
    return a;
}

#define CP16(dst, src) \
    asm volatile("cp.async.cg.shared.global [%0], [%1], 16;" :: "r"(dst), "l"(src) : "memory")
#define CP_COMMIT() asm volatile("cp.async.commit_group;" ::: "memory")
#define CP_WAIT(n)  asm volatile("cp.async.wait_group %0;" :: "n"(n) : "memory")

#define LDSM4(r, addr) \
    asm volatile("ldmatrix.sync.aligned.m8n8.x4.shared.b16 {%0,%1,%2,%3}, [%4];" \
        : "=r"((r)[0]), "=r"((r)[1]), "=r"((r)[2]), "=r"((r)[3]) : "r"(addr))

#define MMA_FP8(d, a, b0, b1) \
    asm volatile("mma.sync.aligned.m16n8k32.row.col.f32.e4m3.e4m3.f32 " \
        "{%0,%1,%2,%3}, {%4,%5,%6,%7}, {%8,%9}, {%0,%1,%2,%3};" \
        : "+f"((d)[0]), "+f"((d)[1]), "+f"((d)[2]), "+f"((d)[3]) \
        : "r"((a)[0]), "r"((a)[1]), "r"((a)[2]), "r"((a)[3]), "r"(b0), "r"(b1))

__device__ __forceinline__ uint8_t f2e4m3(float v) {
    return (uint8_t)__nv_cvt_float_to_fp8(v, __NV_SATFINITE, __NV_E4M3);
}
__device__ __forceinline__ float e4m3f(uint8_t b) {
    __half_raw h = __nv_cvt_fp8_to_halfraw((__nv_fp8_storage_t)b, __NV_E4M3);
    return __half2float(*(__half*)&h);
}
__device__ __forceinline__ bool rt_ok(float v) {
    if (!isfinite(v)) return false;
    return e4m3f(f2e4m3(v)) == v;
}

// ---------------- kernel 1: fused prep (detect + convert/transpose + quant) --
#define PREP_BLKS ((GN / 64) * (GK / 64))             // 4096
#define QUANT_BLKS ((GM * GK) / (256 * 8))            // 8192

__global__ void __launch_bounds__(256) prep_kernel(const void* __restrict__ w,
                                                   const float* __restrict__ x,
                                                   const float* __restrict__ s_in) {
    const int t = threadIdx.x;
    if (blockIdx.x >= PREP_BLKS) {
        // ---- quant part ----
        const float s = *s_in;
        size_t i = (size_t)(blockIdx.x - PREP_BLKS) * 256 + t;   // one per 8 elems
        const float4 a = ((const float4*)x)[i * 2 + 0];
        const float4 b = ((const float4*)x)[i * 2 + 1];
        uint8_t q[8];
        q[0] = f2e4m3(a.x / s); q[1] = f2e4m3(a.y / s);
        q[2] = f2e4m3(a.z / s); q[3] = f2e4m3(a.w / s);
        q[4] = f2e4m3(b.x / s); q[5] = f2e4m3(b.y / s);
        q[6] = f2e4m3(b.z / s); q[7] = f2e4m3(b.w / s);
        ((uint2*)g_q)[i] = *(const uint2*)q;
        return;
    }

    // ---- weight prep part ----
    __shared__ uint8_t tile[64][68];            // [n_local][k_local], padded
    const int n0 = (blockIdx.x & 127) * 64;
    const int k0 = (blockIdx.x >> 7) * 64;

    // Inline dtype detection (fp8 promotion is lossless -> exact round-trip;
    // f32 checked first since f32-promoted data viewed as bf16 also passes).
    const int is_f32  = __syncthreads_and(rt_ok(((const float*)w)[t]));
    int is_bf16 = 0;
    if (!is_f32)
        is_bf16 = __syncthreads_and(rt_ok(__bfloat162float(((const __nv_bfloat16*)w)[t])));

    if (is_f32) {
        const float* wf = (const float*)w;
#pragma unroll
        for (int i = 0; i < 4; i++) {
            int e4 = t + i * 256;               // 1024 float4s in the 64x64 tile
            int r = e4 >> 4, c4 = e4 & 15;      // r = k_local, c4 = float4 over n
            float4 v = *(const float4*)(wf + (size_t)(k0 + r) * GN + n0 + c4 * 4);
            tile[c4 * 4 + 0][r] = f2e4m3(v.x);
            tile[c4 * 4 + 1][r] = f2e4m3(v.y);
            tile[c4 * 4 + 2][r] = f2e4m3(v.z);
            tile[c4 * 4 + 3][r] = f2e4m3(v.w);
        }
    } else if (is_bf16) {
        const __nv_bfloat16* wb = (const __nv_bfloat16*)w;
#pragma unroll
        for (int i = 0; i < 16; i++) {
            int e = t + i * 256;
            int r = e >> 6, c = e & 63;
            tile[c][r] = f2e4m3(__bfloat162float(wb[(size_t)(k0 + r) * GN + n0 + c]));
        }
    } else {
        const uint8_t* w8 = (const uint8_t*)w;
#pragma unroll
        for (int i = 0; i < 4; i++) {
            int idx = t + i * 256;
            int r = idx >> 4, wc = idx & 15;
            uint32_t v = *(const uint32_t*)(w8 + (size_t)(k0 + r) * GN + n0 + wc * 4);
            tile[wc * 4 + 0][r] = (uint8_t)(v);
            tile[wc * 4 + 1][r] = (uint8_t)(v >> 8);
            tile[wc * 4 + 2][r] = (uint8_t)(v >> 16);
            tile[wc * 4 + 3][r] = (uint8_t)(v >> 24);
        }
    }
    __syncthreads();
#pragma unroll
    for (int i = 0; i < 4; i++) {
        int idx = t + i * 256;
        int r = idx >> 4, wc = idx & 15;        // r = n_local, wc = word over k
        uint32_t v = (uint32_t)tile[r][wc * 4 + 0]
                   | ((uint32_t)tile[r][wc * 4 + 1] << 8)
                   | ((uint32_t)tile[r][wc * 4 + 2] << 16)
                   | ((uint32_t)tile[r][wc * 4 + 3] << 24);
        *(uint32_t*)(g_wt + (size_t)(n0 + r) * GK + k0 + wc * 4) = v;
    }
}

// ---------------- kernel 2: FP8 GEMM (mma.sync, 64x64 warp tiles) -----------
// CTA 128x128x128, 4 warps, 3-stage 32KB ring (98KB smem) -> 2 CTAs/SM.
// This is the R12 configuration verbatim — the measured-best GEMM (641.6us):
// loads BEFORE compute, inline sw_off addressing, fragment double-buffering,
// per-warp + CTA-parity kk skew.
#define TILE_M 128
#define TILE_N 128
#define TILE_K 128
#define STAGES 3
#define KT (GK / TILE_K)          // 16
#define NTHREADS 128

static constexpr int A_BYTES     = TILE_M * TILE_K;       // 16384
static constexpr int STAGE_BYTES = 2 * A_BYTES;           // 32768
static constexpr int SMEM_DYN    = STAGES * STAGE_BYTES;  // 98304

// One tile-row per 128B smem row; SW128 XOR of the 16B chunk index.
__device__ __forceinline__ uint32_t sw_off(int row, int kc) {
    return ((uint32_t)row << 7) + ((uint32_t)((kc ^ (row & 7))) << 4);
}

__device__ __forceinline__ void load_stage(uint32_t sb, int tid,
                                           const uint8_t* __restrict__ gA0,
                                           const uint8_t* __restrict__ gB0,
                                           int kt, int s) {
    const uint32_t base = sb + (uint32_t)s * STAGE_BYTES;
    const uint8_t* ga = gA0 + (size_t)kt * TILE_K;
    const uint8_t* gb = gB0 + (size_t)kt * TILE_K;
#pragma unroll
    for (int i = 0; i < 8; i++) {                     // A: 1024 chunks / 128 thr
        int c = tid + i * NTHREADS;
        int r = c >> 3, kc = c & 7;
        CP16(base + sw_off(r, kc), ga + (size_t)r * GK + kc * 16);
    }
#pragma unroll
    for (int i = 0; i < 8; i++) {                     // B: 1024 chunks
        int c = tid + i * NTHREADS;
        int r = c >> 3, kc = c & 7;
        CP16(base + A_BYTES + sw_off(r, kc), gb + (size_t)r * GK + kc * 16);
    }
    CP_COMMIT();
}

struct Frag { float acc[4][8][4]; };   // [m16][n8][quad] — 128 regs

__device__ __forceinline__ void ld_frags(uint32_t stage, int kk,
                                         int a_m, int a_kh, int b_n, int b_kh,
                                         uint32_t a[4][4], uint32_t b[4][4]) {
#pragma unroll
    for (int mt = 0; mt < 4; mt++)
        LDSM4(a[mt], stage + sw_off(a_m + mt * 16, kk * 2 + a_kh));
#pragma unroll
    for (int p = 0; p < 4; p++)
        LDSM4(b[p], stage + A_BYTES + sw_off(b_n + p * 16, kk * 2 + b_kh));
}

__device__ __forceinline__ void mma_frags(Frag& f, uint32_t a[4][4], uint32_t b[4][4]) {
#pragma unroll
    for (int mt = 0; mt < 4; mt++)
#pragma unroll
        for (int p = 0; p < 4; p++) {
            MMA_FP8(f.acc[mt][p * 2 + 0], a[mt], b[p][0], b[p][1]);
            MMA_FP8(f.acc[mt][p * 2 + 1], a[mt], b[p][2], b[p][3]);
        }
}

// Fragments double-buffered; per-warp+per-CTA kk skew so the LDSM windows of
// the two warps sharing an SMSP (same wid, different CTA) anti-phase.
__device__ __forceinline__ void compute_stage(uint32_t stage, Frag& f,
                                              int a_m, int a_kh,
                                              int b_n, int b_kh, int skew) {
    uint32_t a[2][4][4], b[2][4][4];
    ld_frags(stage, skew, a_m, a_kh, b_n, b_kh, a[0], b[0]);
#pragma unroll
    for (int i = 0; i < 4; i++) {
        if (i < 3)
            ld_frags(stage, (skew + i + 1) & 3, a_m, a_kh, b_n, b_kh,
                     a[(i + 1) & 1], b[(i + 1) & 1]);
        mma_frags(f, a[i & 1], b[i & 1]);
    }
}

__global__ void __launch_bounds__(NTHREADS, 1)
gemm_kernel(const float* __restrict__ wscale, const float* __restrict__ iscale,
            const float* __restrict__ bias, float* __restrict__ out) {
    extern __shared__ uint8_t smem[];
    const uint32_t sb = smem_u32(smem);

    const int tid = threadIdx.x, wid = tid >> 5, lane = tid & 31;
    const int warp_m = wid & 1, warp_n = wid >> 1;     // 2x2 warp grid
    const int m0 = blockIdx.y * TILE_M;
    const int n0 = blockIdx.x * TILE_N;
    const int skew = (wid + 2 * ((blockIdx.x + blockIdx.y) & 1)) & 3;

    // ldmatrix lane geometry
    const int a_m  = warp_m * 64 + (lane & 15);        // + mt*16
    const int a_kh = lane >> 4;                        // 16B half of K=32
    const int b_n  = warp_n * 64 + (lane & 7) + ((lane >> 4) << 3);  // + p*16
    const int b_kh = (lane >> 3) & 1;

    Frag f;
#pragma unroll
    for (int i = 0; i < 4; i++)
#pragma unroll
        for (int j = 0; j < 8; j++)
#pragma unroll
            for (int q = 0; q < 4; q++) f.acc[i][j][q] = 0.0f;

    const uint8_t* gA0 = g_q  + (size_t)m0 * GK;
    const uint8_t* gB0 = g_wt + (size_t)n0 * GK;

    // Prologue: stages 0,1 in flight
    load_stage(sb, tid, gA0, gB0, 0, 0);
    load_stage(sb, tid, gA0, gB0, 1, 1);

    int s_cur = 0, s_next = 2;
#pragma unroll 1
    for (int kt = 0; kt < KT - 1; kt++) {
        CP_WAIT(1);            // stage kt data landed
        __syncthreads();       // s_next's old contents fully consumed
        if (kt + 2 < KT)
            load_stage(sb, tid, gA0, gB0, kt + 2, s_next);
        compute_stage(sb + (uint32_t)s_cur * STAGE_BYTES, f, a_m, a_kh, b_n, b_kh, skew);
        if (++s_cur == STAGES) s_cur = 0;
        if (++s_next == STAGES) s_next = 0;
    }
    CP_WAIT(0);
    __syncthreads();
    compute_stage(sb + (uint32_t)s_cur * STAGE_BYTES, f, a_m, a_kh, b_n, b_kh, skew);

    // Epilogue: out = acc * (s_in*s_w) + bias
    const float s = wscale[0] * iscale[0];
    const int g = lane >> 2, tig = lane & 3;
#pragma unroll
    for (int nt = 0; nt < 8; nt++) {
        const int n = n0 + warp_n * 64 + nt * 8 + tig * 2;
        const float2 bv = *(const float2*)(bias + n);
#pragma unroll
        for (int mt = 0; mt < 4; mt++) {
            const int m = m0 + warp_m * 64 + mt * 16 + g;
            float2 v0, v1;
            v0.x = f.acc[mt][nt][0] * s + bv.x;
            v0.y = f.acc[mt][nt][1] * s + bv.y;
            v1.x = f.acc[mt][nt][2] * s + bv.x;
            v1.y = f.acc[mt][nt][3] * s + bv.y;
            *(float2*)(out + (size_t)m * GN + n)       = v0;
            *(float2*)(out + (size_t)(m + 8) * GN + n) = v1;
        }
    }
}

// ---------------- launcher ---------------------------------------------------
extern "C" void kernel_launch(void* const* d_in, const int* in_sizes, int n_in,
                              void* d_out, int out_size) {
    const float*   x      = (const float*)d_in[0];
    const void*    w      = d_in[1];
    const float*   wscale = (const float*)d_in[2];
    const float*   iscale = (const float*)d_in[3];
    const float*   bias   = (const float*)d_in[4];
    float*         out    = (float*)d_out;

    prep_kernel<<<PREP_BLKS + QUANT_BLKS, 256>>>(w, x, iscale);

    cudaFuncSetAttribute(gemm_kernel, cudaFuncAttributeMaxDynamicSharedMemorySize, SMEM_DYN);
    gemm_kernel<<<dim3(GN / TILE_N, GM / TILE_M), NTHREADS, SMEM_DYN>>>(wscale, iscale, bias, out);
}